// round 13
// baseline (speedup 1.0000x reference)
#include <cuda_runtime.h>
#include <cuda_fp16.h>
#include <cstdint>
#include <math.h>

// Problem constants
#define BB 64
#define PP 196
#define DD 768
#define CC 201
#define KP 5
#define NCLS 200
#define NN (BB*PP)        // 12544
#define JJ (CC*KP)        // 1005
#define JPAD 1024

// Output layout
#define OFF_LOGITS 0
#define SZ_LOGITS  (NN*JJ)
#define OFF_IMG    (OFF_LOGITS + SZ_LOGITS)
#define SZ_IMG     (BB*JJ)
#define OFF_CLS    (OFF_IMG + SZ_IMG)
#define SZ_CLS     (BB*NCLS)
#define OFF_ASGN   (OFF_CLS + SZ_CLS)
#define SZ_ASGN    (NN)
#define OFF_PNEW   (OFF_ASGN + SZ_ASGN)
#define SZ_PNEW    (CC*KP*DD)

// Device scratch (int8 split operands + per-row inverse scales)
__device__ __align__(16) char  g_a0[NN*DD];
__device__ __align__(16) char  g_a1[NN*DD];
__device__ __align__(16) char  g_b0[JPAD*DD];
__device__ __align__(16) char  g_b1[JPAD*DD];
__device__ float g_ia[NN];      // 1/sa_row
__device__ float g_ib[JPAD];    // 1/sb_row
__device__ float g_inv[NN];     // 1/||rpt_row||
__device__ float g_sw[NCLS*KP];

// ---------------------------------------------------------------------------
// PTX helpers
// ---------------------------------------------------------------------------
__device__ __forceinline__ void ldsm_x4(uint32_t* r, uint32_t addr) {
    asm volatile("ldmatrix.sync.aligned.m8n8.x4.shared.b16 {%0,%1,%2,%3}, [%4];"
                 : "=r"(r[0]), "=r"(r[1]), "=r"(r[2]), "=r"(r[3]) : "r"(addr));
}
__device__ __forceinline__ void mma_s8(int* d, const uint32_t* a, const uint32_t* b) {
    asm volatile(
        "mma.sync.aligned.m16n8k32.row.col.s32.s8.s8.s32 "
        "{%0,%1,%2,%3}, {%4,%5,%6,%7}, {%8,%9}, {%0,%1,%2,%3};"
        : "+r"(d[0]), "+r"(d[1]), "+r"(d[2]), "+r"(d[3])
        : "r"(a[0]), "r"(a[1]), "r"(a[2]), "r"(a[3]), "r"(b[0]), "r"(b[1]));
}
__device__ __forceinline__ void cpa16(uint32_t smem, const void* g) {
    asm volatile("cp.async.ca.shared.global [%0], [%1], 16;" :: "r"(smem), "l"(g));
}
__device__ __forceinline__ void cpa_commit() {
    asm volatile("cp.async.commit_group;" ::: "memory");
}
template <int N>
__device__ __forceinline__ void cpa_wait() {
    asm volatile("cp.async.wait_group %0;" :: "n"(N) : "memory");
}

// ---------------------------------------------------------------------------
// padding no-op kernel (keeps ncu capture window on the GEMM launch)
// ---------------------------------------------------------------------------
__global__ void pad_kernel() {}

// ---------------------------------------------------------------------------
// Row L2 normalization + int8 two-slice quantization (warp per row)
//   x_norm * sa = A0 + A1/128,  sa = 127/max|row|,  store 1/sa
// ---------------------------------------------------------------------------
__device__ __forceinline__ void quant_row(const float4* src, char* d0, char* d1,
                                          float* inv_scale, int r, int lane) {
    float4 v[6];
    float s = 0.0f, mx = 0.0f;
    #pragma unroll
    for (int i = 0; i < 6; i++) {
        v[i] = src[lane + i*32];
        s += v[i].x*v[i].x + v[i].y*v[i].y + v[i].z*v[i].z + v[i].w*v[i].w;
    }
    #pragma unroll
    for (int o = 16; o > 0; o >>= 1) s += __shfl_xor_sync(0xffffffffu, s, o);
    float inv = 1.0f / fmaxf(sqrtf(s), 1e-12f);
    #pragma unroll
    for (int i = 0; i < 6; i++) {
        mx = fmaxf(mx, fmaxf(fmaxf(fabsf(v[i].x), fabsf(v[i].y)),
                             fmaxf(fabsf(v[i].z), fabsf(v[i].w))));
    }
    mx *= inv;
    #pragma unroll
    for (int o = 16; o > 0; o >>= 1) mx = fmaxf(mx, __shfl_xor_sync(0xffffffffu, mx, o));
    float sa = 127.0f / fmaxf(mx, 1e-6f);
    if (lane == 0) inv_scale[r] = 1.0f / sa;
    #pragma unroll
    for (int i = 0; i < 6; i++) {
        float x[4] = {v[i].x*inv*sa, v[i].y*inv*sa, v[i].z*inv*sa, v[i].w*inv*sa};
        char c0[4], c1[4];
        #pragma unroll
        for (int j = 0; j < 4; j++) {
            int q0 = __float2int_rn(x[j]);
            q0 = max(-127, min(127, q0));
            int q1 = __float2int_rn((x[j] - (float)q0) * 128.0f);
            q1 = max(-127, min(127, q1));
            c0[j] = (char)q0; c1[j] = (char)q1;
        }
        int off = (lane + i*32)*4;
        *(char4*)(d0 + (size_t)r*DD + off) = make_char4(c0[0], c0[1], c0[2], c0[3]);
        *(char4*)(d1 + (size_t)r*DD + off) = make_char4(c1[0], c1[1], c1[2], c1[3]);
    }
}

__global__ __launch_bounds__(256) void norm_kernel(const float* __restrict__ pt,
                            const float* __restrict__ rpt,
                            const float* __restrict__ proto) {
    const int r = blockIdx.x * 8 + (threadIdx.x >> 5);
    const int lane = threadIdx.x & 31;
    if (r >= 2*NN + JPAD) return;

    if (r < NN) {
        quant_row((const float4*)(pt + (size_t)r*DD), g_a0, g_a1, g_ia, r, lane);
    } else if (r < 2*NN) {
        int rr = r - NN;
        const float4* src = (const float4*)(rpt + (size_t)rr*DD);
        float s = 0.0f;
        #pragma unroll
        for (int i = 0; i < 6; i++) {
            float4 v = src[lane + i*32];
            s += v.x*v.x + v.y*v.y + v.z*v.z + v.w*v.w;
        }
        #pragma unroll
        for (int o = 16; o > 0; o >>= 1) s += __shfl_xor_sync(0xffffffffu, s, o);
        if (lane == 0) g_inv[rr] = 1.0f / fmaxf(sqrtf(s), 1e-12f);
    } else {
        int j = r - 2*NN;
        if (j >= JJ) {
            for (int i = lane; i < DD/4; i += 32) {
                *(char4*)(g_b0 + (size_t)j*DD + i*4) = make_char4(0,0,0,0);
                *(char4*)(g_b1 + (size_t)j*DD + i*4) = make_char4(0,0,0,0);
            }
            if (lane == 0) g_ib[j] = 0.0f;
            return;
        }
        quant_row((const float4*)(proto + (size_t)j*DD), g_b0, g_b1, g_ib, j, lane);
    }
}

// ---------------------------------------------------------------------------
// sw = softmax(sa_weights, axis=-1) * K
// ---------------------------------------------------------------------------
__global__ void sw_kernel(const float* __restrict__ sa) {
    int c = blockIdx.x * blockDim.x + threadIdx.x;
    if (c >= NCLS) return;
    float w[KP];
    float m = -1e30f;
    for (int k = 0; k < KP; k++) { w[k] = sa[c*KP+k]; m = fmaxf(m, w[k]); }
    float s = 0.0f;
    for (int k = 0; k < KP; k++) { w[k] = expf(w[k]-m); s += w[k]; }
    for (int k = 0; k < KP; k++) g_sw[c*KP+k] = w[k] / s * 5.0f;
}

// ---------------------------------------------------------------------------
// int8 Ozaki 3-product GEMM:  out = (hi + mid/128) * ia[row] * ib[col]
//   hi  = sum A0*B0 ; mid = sum (A0*B1 + A1*B0)   (both exact int32)
// CTA 128x128, 512 thr = 16 warps (4M x 4N of 32x32), BK=64 (2 k32 slices),
// 2-stage cp.async, 1 CTA/SM.
// ---------------------------------------------------------------------------
#define SAS 40                               // b16 units per smem row (80B)
#define ROW_B 80
#define ARR_B (128*ROW_B)                    // 10240 per array
#define STAGE_B (4*ARR_B)                    // A0,A1,B0,B1 -> 40960 per stage
#define SMEM_GEMM (2*STAGE_B)                // 81920
#define NCHUNK (DD/64)                       // 12

__global__ __launch_bounds__(512, 1) void gemm_mma_kernel(float* __restrict__ out) {
    extern __shared__ __align__(16) char smem[];
    const uint32_t sb = (uint32_t)__cvta_generic_to_shared(smem);

    const int tid  = threadIdx.x;
    const int lane = tid & 31;
    const int wid  = tid >> 5;
    const int wm   = wid & 3;      // M 32-block
    const int wn   = wid >> 2;     // N 32-block (0..3)
    const int bm   = blockIdx.x * 128;
    const int bn   = blockIdx.y * 128;

    const int arow = (lane & 7) + ((lane >> 3) & 1) * 8;
    const int acol = (lane >> 4) * 8;
    const int brow = (lane & 7) + ((lane >> 4) & 1) * 8;
    const int bcol = ((lane >> 3) & 1) * 8;

    int hi[2][4][4], mid[2][4][4];
    #pragma unroll
    for (int i = 0; i < 2; i++)
        #pragma unroll
        for (int j = 0; j < 4; j++)
            #pragma unroll
            for (int q = 0; q < 4; q++) { hi[i][j][q] = 0; mid[i][j][q] = 0; }

    // loader: 2048 16B granules/chunk (4 arrays x 128 rows x 4), 4 per thread
    auto load_chunk = [&](int kt, int s) {
        uint32_t st = sb + s*STAGE_B;
        #pragma unroll
        for (int i = 0; i < 4; i++) {
            int x = i*512 + tid;
            int arr = x >> 9;              // 0 A0, 1 A1, 2 B0, 3 B1
            int rem = x & 511;
            int row = rem >> 2, q = rem & 3;
            uint32_t dst = st + arr*ARR_B + (uint32_t)(row*ROW_B + q*16);
            const char* src;
            if (arr == 0)      src = g_a0 + (size_t)(bm + row)*DD;
            else if (arr == 1) src = g_a1 + (size_t)(bm + row)*DD;
            else if (arr == 2) src = g_b0 + (size_t)(bn + row)*DD;
            else               src = g_b1 + (size_t)(bn + row)*DD;
            cpa16(dst, src + kt + q*16);
        }
        cpa_commit();
    };

    load_chunk(0, 0);

    for (int i = 0; i < NCHUNK; i++) {
        const int s = i & 1;
        if (i + 1 < NCHUNK) {
            load_chunk((i+1)*64, (i+1) & 1);
            cpa_wait<1>();
        } else {
            cpa_wait<0>();
        }
        __syncthreads();

        const uint32_t aA0 = sb + s*STAGE_B;
        const uint32_t aA1 = aA0 + ARR_B;
        const uint32_t aB0 = aA0 + 2*ARR_B;
        const uint32_t aB1 = aA0 + 3*ARR_B;

        #pragma unroll
        for (int ks = 0; ks < 32; ks += 16) {   // two k32 slices (16 b16 each)
            uint32_t a0f[2][4], a1f[2][4];
            #pragma unroll
            for (int mi = 0; mi < 2; mi++) {
                uint32_t off = (uint32_t)((wm*32 + mi*16 + arow)*SAS + ks + acol) * 2;
                ldsm_x4(a0f[mi], aA0 + off);
                ldsm_x4(a1f[mi], aA1 + off);
            }
            #pragma unroll
            for (int nb = 0; nb < 2; nb++) {
                uint32_t b0f[4], b1f[4];
                uint32_t off = (uint32_t)((wn*32 + nb*16 + brow)*SAS + ks + bcol) * 2;
                ldsm_x4(b0f, aB0 + off);
                ldsm_x4(b1f, aB1 + off);
                #pragma unroll
                for (int mi = 0; mi < 2; mi++) {
                    #pragma unroll
                    for (int h = 0; h < 2; h++) {
                        mma_s8(hi[mi][nb*2+h],  a0f[mi], b0f + 2*h);
                        mma_s8(mid[mi][nb*2+h], a0f[mi], b1f + 2*h);
                        mma_s8(mid[mi][nb*2+h], a1f[mi], b0f + 2*h);
                    }
                }
            }
        }
        __syncthreads();
    }

    // epilogue: combine + descale, scalar fp32 stores (JJ odd)
    #pragma unroll
    for (int mi = 0; mi < 2; mi++) {
        #pragma unroll
        for (int nf = 0; nf < 4; nf++) {
            #pragma unroll
            for (int q = 0; q < 4; q++) {
                int rloc = wm*32 + mi*16 + (lane >> 2) + (q >> 1)*8;
                int cloc = wn*32 + nf*8 + (lane & 3)*2 + (q & 1);
                int col = bn + cloc;
                if (col < JJ) {
                    float v = (float)hi[mi][nf][q] + (float)mid[mi][nf][q] * 0.0078125f;
                    out[(size_t)(bm + rloc)*JJ + col] = v * g_ia[bm + rloc] * g_ib[col];
                }
            }
        }
    }
}

// ---------------------------------------------------------------------------
// image_logits[b, j] = max_p logits[b, p, j]
// ---------------------------------------------------------------------------
__global__ void imgmax_kernel(const float* __restrict__ logits, float* __restrict__ img) {
    int t = blockIdx.x * blockDim.x + threadIdx.x;
    if (t >= BB*JJ) return;
    int b = t / JJ, j = t % JJ;
    const float* p = logits + (size_t)b*PP*JJ + j;
    float m = -1e30f;
    for (int i = 0; i < PP; i++) m = fmaxf(m, p[(size_t)i*JJ]);
    img[(size_t)b*JJ + j] = m;
}

// ---------------------------------------------------------------------------
// class_logits[b, c] = sum_k img[b, c, k]*sw[c, k] / TEMP
// ---------------------------------------------------------------------------
__global__ void cls_kernel(const float* __restrict__ img, float* __restrict__ cls) {
    int t = blockIdx.x * blockDim.x + threadIdx.x;
    if (t >= BB*NCLS) return;
    int b = t / NCLS, c = t % NCLS;
    float s = 0.0f;
    #pragma unroll
    for (int k = 0; k < KP; k++) s += img[(size_t)b*JJ + c*KP + k] * g_sw[c*KP+k];
    cls[t] = s / 0.2f;
}

// ---------------------------------------------------------------------------
// Per-class: deterministic compaction + Sinkhorn + assignment + P_new
// ---------------------------------------------------------------------------
#define MAXN 1024
__global__ __launch_bounds__(256) void sinkhorn_kernel(
        const float* __restrict__ logits, const int* __restrict__ labels,
        const float* __restrict__ proto, const float* __restrict__ rpt,
        float* __restrict__ assign, float* __restrict__ pnew) {
    const int c = blockIdx.x;
    const int tid = threadIdx.x;
    const int lane = tid & 31, w = tid >> 5;

    __shared__ int   s_idx[MAXN];
    __shared__ float Q[KP][MAXN];
    __shared__ float red[256];
    __shared__ int   warp_cnt[8], warp_off[8];
    __shared__ int   s_n;

    if (tid == 0) s_n = 0;
    __syncthreads();

    for (int base = 0; base < NN; base += 256) {
        int n = base + tid;
        bool p = (labels[n] == c);
        unsigned bal = __ballot_sync(0xffffffffu, p);
        if (lane == 0) warp_cnt[w] = __popc(bal);
        __syncthreads();
        if (tid == 0) {
            int s = s_n;
            #pragma unroll
            for (int i = 0; i < 8; i++) { warp_off[i] = s; s += warp_cnt[i]; }
            s_n = s;
        }
        __syncthreads();
        if (p) {
            int pos = warp_off[w] + __popc(bal & ((1u << lane) - 1u));
            if (pos < MAXN) s_idx[pos] = n;
        }
        __syncthreads();
    }
    const int Nc = min(s_n, MAXN);

    if (Nc == 0) {
        for (int x = tid; x < KP*DD; x += 256)
            pnew[(size_t)c*KP*DD + x] = proto[(size_t)c*KP*DD + x];
        return;
    }

    for (int i = tid; i < Nc; i += 256) {
        const float* lp = logits + (size_t)s_idx[i]*JJ + c*KP;
        #pragma unroll
        for (int k = 0; k < KP; k++) Q[k][i] = expf(lp[k] * 20.0f);
    }
    __syncthreads();

    float s = 0.0f;
    for (int k = 0; k < KP; k++)
        for (int i = tid; i < Nc; i += 256) s += Q[k][i];
    red[tid] = s; __syncthreads();
    for (int o = 128; o > 0; o >>= 1) { if (tid < o) red[tid] += red[tid+o]; __syncthreads(); }
    float tot = red[0];
    __syncthreads();
    float dTot = (tot > 0.0f) ? tot : 1.0f;
    for (int k = 0; k < KP; k++)
        for (int i = tid; i < Nc; i += 256) Q[k][i] /= dTot;
    __syncthreads();

    const float fNc = (float)Nc;
    for (int it = 0; it < 3; it++) {
        for (int k = 0; k < KP; k++) {
            float rs = 0.0f;
            for (int i = tid; i < Nc; i += 256) rs += Q[k][i];
            red[tid] = rs; __syncthreads();
            for (int o = 128; o > 0; o >>= 1) { if (tid < o) red[tid] += red[tid+o]; __syncthreads(); }
            float r = red[0];
            __syncthreads();
            float dr = (r > 0.0f) ? r : 1.0f;
            for (int i = tid; i < Nc; i += 256) Q[k][i] = Q[k][i] / dr / 5.0f;
            __syncthreads();
        }
        for (int i = tid; i < Nc; i += 256) {
            float cs = Q[0][i]+Q[1][i]+Q[2][i]+Q[3][i]+Q[4][i];
            float dc = (cs > 0.0f) ? cs : 1.0f;
            #pragma unroll
            for (int k = 0; k < KP; k++) Q[k][i] = Q[k][i] / dc / fNc;
        }
        __syncthreads();
    }
    for (int k = 0; k < KP; k++)
        for (int i = tid; i < Nc; i += 256) Q[k][i] *= fNc;
    __syncthreads();

    for (int i = tid; i < Nc; i += 256) {
        float best = Q[0][i]; int ba = 0;
        #pragma unroll
        for (int k = 1; k < KP; k++) if (Q[k][i] > best) { best = Q[k][i]; ba = k; }
        assign[s_idx[i]] = (float)(c*KP + ba);
    }
    __syncthreads();

    for (int i = tid; i < Nc; i += 256) {
        float inv = g_inv[s_idx[i]];
        #pragma unroll
        for (int k = 0; k < KP; k++) Q[k][i] *= inv;
    }
    __syncthreads();

    const int d0 = tid * 3;
    float acc[KP][3];
    #pragma unroll
    for (int k = 0; k < KP; k++) { acc[k][0]=0.f; acc[k][1]=0.f; acc[k][2]=0.f; }
    for (int i = 0; i < Nc; i++) {
        const float* xp = rpt + (size_t)s_idx[i]*DD + d0;
        float x0 = xp[0], x1 = xp[1], x2 = xp[2];
        #pragma unroll
        for (int k = 0; k < KP; k++) {
            float q = Q[k][i];
            acc[k][0] = fmaf(q, x0, acc[k][0]);
            acc[k][1] = fmaf(q, x1, acc[k][1]);
            acc[k][2] = fmaf(q, x2, acc[k][2]);
        }
    }
    const float g = 0.999f, og = 1.0f - 0.999f;
    #pragma unroll
    for (int k = 0; k < KP; k++) {
        size_t basep = ((size_t)c*KP + k)*DD + d0;
        #pragma unroll
        for (int j = 0; j < 3; j++)
            pnew[basep + j] = g * proto[basep + j] + og * acc[k][j];
    }
}

// ---------------------------------------------------------------------------
extern "C" void kernel_launch(void* const* d_in, const int* in_sizes, int n_in,
                              void* d_out, int out_size) {
    const float* pt    = (const float*)d_in[0];
    const float* rpt   = (const float*)d_in[1];
    const float* proto = (const float*)d_in[2];
    const float* sa    = (const float*)d_in[3];
    const int*   lbl   = (const int*)  d_in[4];
    float* out = (float*)d_out;

    cudaFuncSetAttribute(gemm_mma_kernel,
                         cudaFuncAttributeMaxDynamicSharedMemorySize, SMEM_GEMM);

    pad_kernel<<<1, 32>>>();                              // keeps ncu window on GEMM
    norm_kernel<<<(2*NN + JPAD + 7)/8, 256>>>(pt, rpt, proto);
    sw_kernel<<<1, 256>>>(sa);
    {
        dim3 grid(NN/128, JPAD/128);   // 98 x 8
        gemm_mma_kernel<<<grid, 512, SMEM_GEMM>>>(out + OFF_LOGITS);
    }
    imgmax_kernel<<<(BB*JJ + 255)/256, 256>>>(out + OFF_LOGITS, out + OFF_IMG);
    cls_kernel<<<(BB*NCLS + 255)/256, 256>>>(out + OFF_IMG, out + OFF_CLS);
    sinkhorn_kernel<<<CC, 256>>>(out + OFF_LOGITS, lbl, proto, rpt,
                                 out + OFF_ASGN, out + OFF_PNEW);
}

// round 14
// speedup vs baseline: 2.3745x; 2.3745x over previous
#include <cuda_runtime.h>
#include <cuda_fp16.h>
#include <cstdint>
#include <math.h>

// Problem constants
#define BB 64
#define PP 196
#define DD 768
#define CC 201
#define KP 5
#define NCLS 200
#define NN (BB*PP)        // 12544
#define JJ (CC*KP)        // 1005
#define JPAD 1024
#define NBATCH (NN/256)   // 49

// Output layout
#define OFF_LOGITS 0
#define SZ_LOGITS  (NN*JJ)
#define OFF_IMG    (OFF_LOGITS + SZ_LOGITS)
#define SZ_IMG     (BB*JJ)
#define OFF_CLS    (OFF_IMG + SZ_IMG)
#define SZ_CLS     (BB*NCLS)
#define OFF_ASGN   (OFF_CLS + SZ_CLS)
#define SZ_ASGN    (NN)
#define OFF_PNEW   (OFF_ASGN + SZ_ASGN)
#define SZ_PNEW    (CC*KP*DD)

// Device scratch
__device__ __align__(16) __half g_pth[NN*DD];     // fp16(A)
__device__ __align__(16) __half g_pt2[NN*DD];     // fp16(Ah + 64*(A-Ah))
__device__ __align__(16) __half g_pnh[JPAD*DD];   // fp16(B)
__device__ __align__(16) __half g_pn2[JPAD*DD];   // fp16(Bh + 64*(B-Bh))
__device__ float g_inv[NN];                       // 1/||rpt_row||
__device__ float g_sw[NCLS*KP];

// ---------------------------------------------------------------------------
// PTX helpers
// ---------------------------------------------------------------------------
__device__ __forceinline__ void ldsm_x4(uint32_t* r, uint32_t addr) {
    asm volatile("ldmatrix.sync.aligned.m8n8.x4.shared.b16 {%0,%1,%2,%3}, [%4];"
                 : "=r"(r[0]), "=r"(r[1]), "=r"(r[2]), "=r"(r[3]) : "r"(addr));
}
__device__ __forceinline__ void mma_fp16(float* d, const uint32_t* a, const uint32_t* b) {
    asm volatile(
        "mma.sync.aligned.m16n8k16.row.col.f32.f16.f16.f32 "
        "{%0,%1,%2,%3}, {%4,%5,%6,%7}, {%8,%9}, {%0,%1,%2,%3};"
        : "+f"(d[0]), "+f"(d[1]), "+f"(d[2]), "+f"(d[3])
        : "r"(a[0]), "r"(a[1]), "r"(a[2]), "r"(a[3]), "r"(b[0]), "r"(b[1]));
}
__device__ __forceinline__ void cpa16(uint32_t smem, const void* g) {
    asm volatile("cp.async.ca.shared.global [%0], [%1], 16;" :: "r"(smem), "l"(g));
}
__device__ __forceinline__ void cpa_commit() {
    asm volatile("cp.async.commit_group;" ::: "memory");
}
template <int N>
__device__ __forceinline__ void cpa_wait() {
    asm volatile("cp.async.wait_group %0;" :: "n"(N) : "memory");
}

// ---------------------------------------------------------------------------
// padding no-op kernel (keeps ncu capture window on the GEMM launch)
// ---------------------------------------------------------------------------
__global__ void pad_kernel() {}

// ---------------------------------------------------------------------------
// Row L2 normalization + fp16 Ootomo split (warp per row, float4 loads)
// ---------------------------------------------------------------------------
__global__ __launch_bounds__(256) void norm_kernel(const float* __restrict__ pt,
                            const float* __restrict__ rpt,
                            const float* __restrict__ proto) {
    const int r = blockIdx.x * 8 + (threadIdx.x >> 5);
    const int lane = threadIdx.x & 31;
    if (r >= 2*NN + JPAD) return;

    if (r < NN) {
        const float4* src = (const float4*)(pt + (size_t)r*DD);
        float s = 0.0f;
        float4 v[6];
        #pragma unroll
        for (int i = 0; i < 6; i++) {
            v[i] = src[lane + i*32];
            s += v[i].x*v[i].x + v[i].y*v[i].y + v[i].z*v[i].z + v[i].w*v[i].w;
        }
        #pragma unroll
        for (int o = 16; o > 0; o >>= 1) s += __shfl_xor_sync(0xffffffffu, s, o);
        float inv = 1.0f / fmaxf(sqrtf(s), 1e-12f);
        #pragma unroll
        for (int i = 0; i < 6; i++) {
            float x[4] = {v[i].x*inv, v[i].y*inv, v[i].z*inv, v[i].w*inv};
            __half2 h2[2], l2[2];
            #pragma unroll
            for (int j = 0; j < 2; j++) {
                __half h0 = __float2half(x[j*2]),  h1 = __float2half(x[j*2+1]);
                float f0 = __half2float(h0),        f1 = __half2float(h1);
                h2[j] = __halves2half2(h0, h1);
                l2[j] = __halves2half2(__float2half(fmaf(64.0f, x[j*2]-f0, f0)),
                                       __float2half(fmaf(64.0f, x[j*2+1]-f1, f1)));
            }
            size_t o4 = (size_t)r*DD + (lane + i*32)*4;
            *(__half2*)(g_pth + o4)     = h2[0];
            *(__half2*)(g_pth + o4 + 2) = h2[1];
            *(__half2*)(g_pt2 + o4)     = l2[0];
            *(__half2*)(g_pt2 + o4 + 2) = l2[1];
        }
    } else if (r < 2*NN) {
        int rr = r - NN;
        const float4* src = (const float4*)(rpt + (size_t)rr*DD);
        float s = 0.0f;
        #pragma unroll
        for (int i = 0; i < 6; i++) {
            float4 v = src[lane + i*32];
            s += v.x*v.x + v.y*v.y + v.z*v.z + v.w*v.w;
        }
        #pragma unroll
        for (int o = 16; o > 0; o >>= 1) s += __shfl_xor_sync(0xffffffffu, s, o);
        if (lane == 0) g_inv[rr] = 1.0f / fmaxf(sqrtf(s), 1e-12f);
    } else {
        int j = r - 2*NN;
        if (j >= JJ) {
            __half z = __float2half(0.0f);
            for (int i = lane; i < DD; i += 32) {
                g_pnh[(size_t)j*DD + i] = z;
                g_pn2[(size_t)j*DD + i] = z;
            }
            return;
        }
        const float* src = proto + (size_t)j*DD;
        float s = 0.0f;
        for (int i = lane; i < DD; i += 32) { float v = src[i]; s += v*v; }
        #pragma unroll
        for (int o = 16; o > 0; o >>= 1) s += __shfl_xor_sync(0xffffffffu, s, o);
        float inv = 1.0f / fmaxf(sqrtf(s), 1e-12f);
        for (int i = lane; i < DD; i += 32) {
            float x = src[i] * inv;
            __half h = __float2half(x);
            float hf = __half2float(h);
            g_pnh[(size_t)j*DD + i] = h;
            g_pn2[(size_t)j*DD + i] = __float2half(fmaf(64.0f, x - hf, hf));
        }
    }
}

// ---------------------------------------------------------------------------
// sw = softmax(sa_weights, axis=-1) * K
// ---------------------------------------------------------------------------
__global__ void sw_kernel(const float* __restrict__ sa) {
    int c = blockIdx.x * blockDim.x + threadIdx.x;
    if (c >= NCLS) return;
    float w[KP];
    float m = -1e30f;
    for (int k = 0; k < KP; k++) { w[k] = sa[c*KP+k]; m = fmaxf(m, w[k]); }
    float s = 0.0f;
    for (int k = 0; k < KP; k++) { w[k] = expf(w[k]-m); s += w[k]; }
    for (int k = 0; k < KP; k++) g_sw[c*KP+k] = w[k] / s * 5.0f;
}

// ---------------------------------------------------------------------------
// 2-product fp16 GEMM (Ootomo, product-split warps):  out = P0 + (P1-P0)/64
// CTA 128x128, 512 thr = 16 warps: tile (wid&7) = 4Mx2N of 32x64 per product,
// product = wid>>3.  BK=64, 2-stage cp.async, 1 CTA/SM.   (R12 config)
// ---------------------------------------------------------------------------
#define SAS2 72
#define ROW_B 144
#define ARR_B (128*ROW_B)                    // 18432 per array
#define STAGE_B (4*ARR_B)                    // 73728 per stage
#define SMEM_GEMM (2*STAGE_B)                // 147456
#define NCHUNK (DD/64)                       // 12

__global__ __launch_bounds__(512, 1) void gemm_mma_kernel(float* __restrict__ out) {
    extern __shared__ __align__(16) char smem[];
    const uint32_t sb = (uint32_t)__cvta_generic_to_shared(smem);

    const int tid  = threadIdx.x;
    const int lane = tid & 31;
    const int wid  = tid >> 5;
    const int p    = wid >> 3;
    const int t    = wid & 7;
    const int wm   = t & 3;
    const int wn   = t >> 2;
    const int bm   = blockIdx.x * 128;
    const int bn   = blockIdx.y * 128;

    const int arow = (lane & 7) + ((lane >> 3) & 1) * 8;
    const int acol = (lane >> 4) * 8;
    const int brow = (lane & 7) + ((lane >> 4) & 1) * 8;
    const int bcol = ((lane >> 3) & 1) * 8;

    const uint32_t offA = (uint32_t)p * ARR_B;
    const uint32_t offB = (uint32_t)(2 + p) * ARR_B;

    float acc[2][8][4];
    #pragma unroll
    for (int i = 0; i < 2; i++)
        #pragma unroll
        for (int j = 0; j < 8; j++)
            #pragma unroll
            for (int q = 0; q < 4; q++) acc[i][j][q] = 0.0f;

    auto load_chunk = [&](int kt, int s) {
        uint32_t st = sb + s*STAGE_B;
        #pragma unroll
        for (int i = 0; i < 8; i++) {
            int x = i*512 + tid;
            int arr = x >> 10;
            int rem = x & 1023;
            int row = rem >> 3, q = rem & 7;
            uint32_t dst = st + arr*ARR_B + (uint32_t)(row*ROW_B + q*16);
            const __half* src;
            if (arr == 0)      src = g_pth + (size_t)(bm + row)*DD;
            else if (arr == 1) src = g_pt2 + (size_t)(bm + row)*DD;
            else if (arr == 2) src = g_pnh + (size_t)(bn + row)*DD;
            else               src = g_pn2 + (size_t)(bn + row)*DD;
            cpa16(dst, src + kt + q*8);
        }
        cpa_commit();
    };

    load_chunk(0, 0);

    for (int i = 0; i < NCHUNK; i++) {
        const int s = i & 1;
        if (i + 1 < NCHUNK) {
            load_chunk((i+1)*64, (i+1) & 1);
            cpa_wait<1>();
        } else {
            cpa_wait<0>();
        }
        __syncthreads();

        const uint32_t aA = sb + s*STAGE_B + offA;
        const uint32_t aB = sb + s*STAGE_B + offB;

        #pragma unroll
        for (int ks = 0; ks < 64; ks += 16) {
            uint32_t af[2][4];
            #pragma unroll
            for (int mi = 0; mi < 2; mi++) {
                uint32_t off = (uint32_t)((wm*32 + mi*16 + arow)*SAS2 + ks + acol) * 2;
                ldsm_x4(af[mi], aA + off);
            }
            #pragma unroll
            for (int nb = 0; nb < 4; nb++) {
                uint32_t bf[4];
                uint32_t off = (uint32_t)((wn*64 + nb*16 + brow)*SAS2 + ks + bcol) * 2;
                ldsm_x4(bf, aB + off);
                #pragma unroll
                for (int mi = 0; mi < 2; mi++) {
                    mma_fp16(acc[mi][nb*2+0], af[mi], bf+0);
                    mma_fp16(acc[mi][nb*2+1], af[mi], bf+2);
                }
            }
        }
        __syncthreads();
    }

    // epilogue: P1 warps stage to smem; P0 combine+store
    float* xbuf = (float*)smem;
    if (p == 1) {
        float* tb = xbuf + t*2048;
        #pragma unroll
        for (int mi = 0; mi < 2; mi++)
            #pragma unroll
            for (int nf = 0; nf < 8; nf++)
                #pragma unroll
                for (int q = 0; q < 4; q++) {
                    int row = mi*16 + (lane >> 2) + (q >> 1)*8;
                    int col = nf*8 + (lane & 3)*2 + (q & 1);
                    tb[row*64 + col] = acc[mi][nf][q];
                }
    }
    __syncthreads();
    if (p == 0) {
        const float* tb = xbuf + t*2048;
        #pragma unroll
        for (int mi = 0; mi < 2; mi++)
            #pragma unroll
            for (int nf = 0; nf < 8; nf++)
                #pragma unroll
                for (int q = 0; q < 4; q++) {
                    int rloc = mi*16 + (lane >> 2) + (q >> 1)*8;
                    int cloc = nf*8 + (lane & 3)*2 + (q & 1);
                    int col = bn + wn*64 + cloc;
                    if (col < JJ) {
                        float p0 = acc[mi][nf][q];
                        float p1 = tb[rloc*64 + cloc];
                        out[(size_t)(bm + wm*32 + rloc)*JJ + col] =
                            p0 + (p1 - p0) * 0.015625f;
                    }
                }
    }
}

// ---------------------------------------------------------------------------
// image_logits[b, j] = max_p logits[b, p, j]
// ---------------------------------------------------------------------------
__global__ void imgmax_kernel(const float* __restrict__ logits, float* __restrict__ img) {
    int t = blockIdx.x * blockDim.x + threadIdx.x;
    if (t >= BB*JJ) return;
    int b = t / JJ, j = t % JJ;
    const float* p = logits + (size_t)b*PP*JJ + j;
    float m = -1e30f;
    for (int i = 0; i < PP; i++) m = fmaxf(m, p[(size_t)i*JJ]);
    img[(size_t)b*JJ + j] = m;
}

// ---------------------------------------------------------------------------
// class_logits[b, c] = sum_k img[b, c, k]*sw[c, k] / TEMP
// ---------------------------------------------------------------------------
__global__ void cls_kernel(const float* __restrict__ img, float* __restrict__ cls) {
    int t = blockIdx.x * blockDim.x + threadIdx.x;
    if (t >= BB*NCLS) return;
    int b = t / NCLS, c = t % NCLS;
    float s = 0.0f;
    #pragma unroll
    for (int k = 0; k < KP; k++) s += img[(size_t)b*JJ + c*KP + k] * g_sw[c*KP+k];
    cls[t] = s / 0.2f;
}

// ---------------------------------------------------------------------------
// Per-class Sinkhorn: two-phase ballot compaction (2 syncs total),
// ILP-4 P_new accumulation.
// ---------------------------------------------------------------------------
#define MAXN 1024
__global__ __launch_bounds__(256) void sinkhorn_kernel(
        const float* __restrict__ logits, const int* __restrict__ labels,
        const float* __restrict__ proto, const float* __restrict__ rpt,
        float* __restrict__ assign, float* __restrict__ pnew) {
    const int c = blockIdx.x;
    const int tid = threadIdx.x;
    const int lane = tid & 31, w = tid >> 5;

    __shared__ int   s_idx[MAXN];
    __shared__ float Q[KP][MAXN];
    __shared__ float red[256];
    __shared__ unsigned s_ball[NBATCH*8];        // 392 ballots
    __shared__ int   s_boff[NBATCH*8];           // exclusive offsets per (batch,warp)
    __shared__ int   s_n;

    // phase A: all ballots, no intermediate syncs (loads pipeline freely)
    unsigned myball[NBATCH];
    #pragma unroll 7
    for (int b = 0; b < NBATCH; b++) {
        int n = b*256 + tid;
        bool p = (labels[n] == c);
        myball[b] = __ballot_sync(0xffffffffu, p);
        if (lane == 0) s_ball[b*8 + w] = myball[b];
    }
    __syncthreads();
    // scan by thread 0 (392 popc+add)
    if (tid == 0) {
        int s = 0;
        for (int i = 0; i < NBATCH*8; i++) {
            s_boff[i] = s;
            s += __popc(s_ball[i]);
        }
        s_n = s;
    }
    __syncthreads();
    const int Nc = min(s_n, MAXN);

    if (Nc == 0) {
        for (int x = tid; x < KP*DD; x += 256)
            pnew[(size_t)c*KP*DD + x] = proto[(size_t)c*KP*DD + x];
        return;
    }

    // phase B: write positions from registers + smem offsets (no reloads)
    #pragma unroll 7
    for (int b = 0; b < NBATCH; b++) {
        unsigned bal = myball[b];
        if ((bal >> lane) & 1u) {
            int pos = s_boff[b*8 + w] + __popc(bal & ((1u << lane) - 1u));
            if (pos < MAXN) s_idx[pos] = b*256 + tid;
        }
    }
    __syncthreads();

    for (int i = tid; i < Nc; i += 256) {
        const float* lp = logits + (size_t)s_idx[i]*JJ + c*KP;
        #pragma unroll
        for (int k = 0; k < KP; k++) Q[k][i] = expf(lp[k] * 20.0f);
    }
    __syncthreads();

    float s = 0.0f;
    for (int k = 0; k < KP; k++)
        for (int i = tid; i < Nc; i += 256) s += Q[k][i];
    red[tid] = s; __syncthreads();
    for (int o = 128; o > 0; o >>= 1) { if (tid < o) red[tid] += red[tid+o]; __syncthreads(); }
    float tot = red[0];
    __syncthreads();
    float dTot = (tot > 0.0f) ? tot : 1.0f;
    for (int k = 0; k < KP; k++)
        for (int i = tid; i < Nc; i += 256) Q[k][i] /= dTot;
    __syncthreads();

    const float fNc = (float)Nc;
    for (int it = 0; it < 3; it++) {
        for (int k = 0; k < KP; k++) {
            float rs = 0.0f;
            for (int i = tid; i < Nc; i += 256) rs += Q[k][i];
            red[tid] = rs; __syncthreads();
            for (int o = 128; o > 0; o >>= 1) { if (tid < o) red[tid] += red[tid+o]; __syncthreads(); }
            float r = red[0];
            __syncthreads();
            float dr = (r > 0.0f) ? r : 1.0f;
            for (int i = tid; i < Nc; i += 256) Q[k][i] = Q[k][i] / dr / 5.0f;
            __syncthreads();
        }
        for (int i = tid; i < Nc; i += 256) {
            float cs = Q[0][i]+Q[1][i]+Q[2][i]+Q[3][i]+Q[4][i];
            float dc = (cs > 0.0f) ? cs : 1.0f;
            #pragma unroll
            for (int k = 0; k < KP; k++) Q[k][i] = Q[k][i] / dc / fNc;
        }
        __syncthreads();
    }
    for (int k = 0; k < KP; k++)
        for (int i = tid; i < Nc; i += 256) Q[k][i] *= fNc;
    __syncthreads();

    for (int i = tid; i < Nc; i += 256) {
        float best = Q[0][i]; int ba = 0;
        #pragma unroll
        for (int k = 1; k < KP; k++) if (Q[k][i] > best) { best = Q[k][i]; ba = k; }
        assign[s_idx[i]] = (float)(c*KP + ba);
    }
    __syncthreads();

    // fold row inverse-norm into Q
    for (int i = tid; i < Nc; i += 256) {
        float inv = g_inv[s_idx[i]];
        #pragma unroll
        for (int k = 0; k < KP; k++) Q[k][i] *= inv;
    }
    __syncthreads();

    // P_new with ILP-4 over i (exact same summation order as serial? no —
    // order preserved: j-th term still added j-th per accumulator lane; the
    // 4 streams interleave but each acc[k][d] receives terms in i order)
    const int d0 = tid * 3;
    float acc[KP][3];
    #pragma unroll
    for (int k = 0; k < KP; k++) { acc[k][0]=0.f; acc[k][1]=0.f; acc[k][2]=0.f; }
    int i = 0;
    for (; i + 4 <= Nc; i += 4) {
        const float* xp0 = rpt + (size_t)s_idx[i+0]*DD + d0;
        const float* xp1 = rpt + (size_t)s_idx[i+1]*DD + d0;
        const float* xp2 = rpt + (size_t)s_idx[i+2]*DD + d0;
        const float* xp3 = rpt + (size_t)s_idx[i+3]*DD + d0;
        float a0 = xp0[0], a1 = xp0[1], a2 = xp0[2];
        float b0 = xp1[0], b1 = xp1[1], b2 = xp1[2];
        float c0 = xp2[0], c1 = xp2[1], c2 = xp2[2];
        float e0 = xp3[0], e1 = xp3[1], e2 = xp3[2];
        #pragma unroll
        for (int k = 0; k < KP; k++) {
            float q0 = Q[k][i+0], q1 = Q[k][i+1], q2 = Q[k][i+2], q3 = Q[k][i+3];
            acc[k][0] = fmaf(q0, a0, acc[k][0]);
            acc[k][1] = fmaf(q0, a1, acc[k][1]);
            acc[k][2] = fmaf(q0, a2, acc[k][2]);
            acc[k][0] = fmaf(q1, b0, acc[k][0]);
            acc[k][1] = fmaf(q1, b1, acc[k][1]);
            acc[k][2] = fmaf(q1, b2, acc[k][2]);
            acc[k][0] = fmaf(q2, c0, acc[k][0]);
            acc[k][1] = fmaf(q2, c1, acc[k][1]);
            acc[k][2] = fmaf(q2, c2, acc[k][2]);
            acc[k][0] = fmaf(q3, e0, acc[k][0]);
            acc[k][1] = fmaf(q3, e1, acc[k][1]);
            acc[k][2] = fmaf(q3, e2, acc[k][2]);
        }
    }
    for (; i < Nc; i++) {
        const float* xp = rpt + (size_t)s_idx[i]*DD + d0;
        float x0 = xp[0], x1 = xp[1], x2 = xp[2];
        #pragma unroll
        for (int k = 0; k < KP; k++) {
            float q = Q[k][i];
            acc[k][0] = fmaf(q, x0, acc[k][0]);
            acc[k][1] = fmaf(q, x1, acc[k][1]);
            acc[k][2] = fmaf(q, x2, acc[k][2]);
        }
    }
    const float g = 0.999f, og = 1.0f - 0.999f;
    #pragma unroll
    for (int k = 0; k < KP; k++) {
        size_t basep = ((size_t)c*KP + k)*DD + d0;
        #pragma unroll
        for (int j = 0; j < 3; j++)
            pnew[basep + j] = g * proto[basep + j] + og * acc[k][j];
    }
}

// ---------------------------------------------------------------------------
extern "C" void kernel_launch(void* const* d_in, const int* in_sizes, int n_in,
                              void* d_out, int out_size) {
    const float* pt    = (const float*)d_in[0];
    const float* rpt   = (const float*)d_in[1];
    const float* proto = (const float*)d_in[2];
    const float* sa    = (const float*)d_in[3];
    const int*   lbl   = (const int*)  d_in[4];
    float* out = (float*)d_out;

    cudaFuncSetAttribute(gemm_mma_kernel,
                         cudaFuncAttributeMaxDynamicSharedMemorySize, SMEM_GEMM);

    pad_kernel<<<1, 32>>>();                              // keeps ncu window on GEMM
    norm_kernel<<<(2*NN + JPAD + 7)/8, 256>>>(pt, rpt, proto);
    sw_kernel<<<1, 256>>>(sa);
    {
        dim3 grid(NN/128, JPAD/128);   // 98 x 8
        gemm_mma_kernel<<<grid, 512, SMEM_GEMM>>>(out + OFF_LOGITS);
    }
    imgmax_kernel<<<(BB*JJ + 255)/256, 256>>>(out + OFF_LOGITS, out + OFF_IMG);
    cls_kernel<<<(BB*NCLS + 255)/256, 256>>>(out + OFF_IMG, out + OFF_CLS);
    sinkhorn_kernel<<<CC, 256>>>(out + OFF_LOGITS, lbl, proto, rpt,
                                 out + OFF_ASGN, out + OFF_PNEW);
}

// round 15
// speedup vs baseline: 2.4112x; 1.0155x over previous
#include <cuda_runtime.h>
#include <cuda_fp16.h>
#include <cstdint>
#include <math.h>

// Problem constants
#define BB 64
#define PP 196
#define DD 768
#define CC 201
#define KP 5
#define NCLS 200
#define NN (BB*PP)        // 12544
#define JJ (CC*KP)        // 1005
#define JPAD 1024
#define NBATCH (NN/256)   // 49

// Output layout
#define OFF_LOGITS 0
#define SZ_LOGITS  (NN*JJ)
#define OFF_IMG    (OFF_LOGITS + SZ_LOGITS)
#define SZ_IMG     (BB*JJ)
#define OFF_CLS    (OFF_IMG + SZ_IMG)
#define SZ_CLS     (BB*NCLS)
#define OFF_ASGN   (OFF_CLS + SZ_CLS)
#define SZ_ASGN    (NN)
#define OFF_PNEW   (OFF_ASGN + SZ_ASGN)
#define SZ_PNEW    (CC*KP*DD)

// Device scratch
__device__ __align__(16) __half g_pth[NN*DD];     // fp16(A)
__device__ __align__(16) __half g_pt2[NN*DD];     // fp16(Ah + 64*(A-Ah))
__device__ __align__(16) __half g_pnh[JPAD*DD];   // fp16(B)
__device__ __align__(16) __half g_pn2[JPAD*DD];   // fp16(Bh + 64*(B-Bh))
__device__ float g_inv[NN];                       // 1/||rpt_row||
__device__ float g_sw[NCLS*KP];

// ---------------------------------------------------------------------------
// PTX helpers
// ---------------------------------------------------------------------------
__device__ __forceinline__ void ldsm_x4(uint32_t* r, uint32_t addr) {
    asm volatile("ldmatrix.sync.aligned.m8n8.x4.shared.b16 {%0,%1,%2,%3}, [%4];"
                 : "=r"(r[0]), "=r"(r[1]), "=r"(r[2]), "=r"(r[3]) : "r"(addr));
}
__device__ __forceinline__ void mma_fp16(float* d, const uint32_t* a, const uint32_t* b) {
    asm volatile(
        "mma.sync.aligned.m16n8k16.row.col.f32.f16.f16.f32 "
        "{%0,%1,%2,%3}, {%4,%5,%6,%7}, {%8,%9}, {%0,%1,%2,%3};"
        : "+f"(d[0]), "+f"(d[1]), "+f"(d[2]), "+f"(d[3])
        : "r"(a[0]), "r"(a[1]), "r"(a[2]), "r"(a[3]), "r"(b[0]), "r"(b[1]));
}
__device__ __forceinline__ void cpa16(uint32_t smem, const void* g) {
    asm volatile("cp.async.ca.shared.global [%0], [%1], 16;" :: "r"(smem), "l"(g));
}
__device__ __forceinline__ void cpa_commit() {
    asm volatile("cp.async.commit_group;" ::: "memory");
}
template <int N>
__device__ __forceinline__ void cpa_wait() {
    asm volatile("cp.async.wait_group %0;" :: "n"(N) : "memory");
}

// ---------------------------------------------------------------------------
// padding no-op kernel (keeps ncu capture window on the GEMM launch)
// ---------------------------------------------------------------------------
__global__ void pad_kernel() {}

// ---------------------------------------------------------------------------
// Row L2 normalization + fp16 Ootomo split (warp per row, float4 loads)
// ---------------------------------------------------------------------------
__global__ __launch_bounds__(256) void norm_kernel(const float* __restrict__ pt,
                            const float* __restrict__ rpt,
                            const float* __restrict__ proto) {
    const int r = blockIdx.x * 8 + (threadIdx.x >> 5);
    const int lane = threadIdx.x & 31;
    if (r >= 2*NN + JPAD) return;

    if (r < NN) {
        const float4* src = (const float4*)(pt + (size_t)r*DD);
        float s = 0.0f;
        float4 v[6];
        #pragma unroll
        for (int i = 0; i < 6; i++) {
            v[i] = src[lane + i*32];
            s += v[i].x*v[i].x + v[i].y*v[i].y + v[i].z*v[i].z + v[i].w*v[i].w;
        }
        #pragma unroll
        for (int o = 16; o > 0; o >>= 1) s += __shfl_xor_sync(0xffffffffu, s, o);
        float inv = 1.0f / fmaxf(sqrtf(s), 1e-12f);
        #pragma unroll
        for (int i = 0; i < 6; i++) {
            float x[4] = {v[i].x*inv, v[i].y*inv, v[i].z*inv, v[i].w*inv};
            __half2 h2[2], l2[2];
            #pragma unroll
            for (int j = 0; j < 2; j++) {
                __half h0 = __float2half(x[j*2]),  h1 = __float2half(x[j*2+1]);
                float f0 = __half2float(h0),        f1 = __half2float(h1);
                h2[j] = __halves2half2(h0, h1);
                l2[j] = __halves2half2(__float2half(fmaf(64.0f, x[j*2]-f0, f0)),
                                       __float2half(fmaf(64.0f, x[j*2+1]-f1, f1)));
            }
            size_t o4 = (size_t)r*DD + (lane + i*32)*4;
            *(__half2*)(g_pth + o4)     = h2[0];
            *(__half2*)(g_pth + o4 + 2) = h2[1];
            *(__half2*)(g_pt2 + o4)     = l2[0];
            *(__half2*)(g_pt2 + o4 + 2) = l2[1];
        }
    } else if (r < 2*NN) {
        int rr = r - NN;
        const float4* src = (const float4*)(rpt + (size_t)rr*DD);
        float s = 0.0f;
        #pragma unroll
        for (int i = 0; i < 6; i++) {
            float4 v = src[lane + i*32];
            s += v.x*v.x + v.y*v.y + v.z*v.z + v.w*v.w;
        }
        #pragma unroll
        for (int o = 16; o > 0; o >>= 1) s += __shfl_xor_sync(0xffffffffu, s, o);
        if (lane == 0) g_inv[rr] = 1.0f / fmaxf(sqrtf(s), 1e-12f);
    } else {
        int j = r - 2*NN;
        if (j >= JJ) {
            __half z = __float2half(0.0f);
            for (int i = lane; i < DD; i += 32) {
                g_pnh[(size_t)j*DD + i] = z;
                g_pn2[(size_t)j*DD + i] = z;
            }
            return;
        }
        const float* src = proto + (size_t)j*DD;
        float s = 0.0f;
        for (int i = lane; i < DD; i += 32) { float v = src[i]; s += v*v; }
        #pragma unroll
        for (int o = 16; o > 0; o >>= 1) s += __shfl_xor_sync(0xffffffffu, s, o);
        float inv = 1.0f / fmaxf(sqrtf(s), 1e-12f);
        for (int i = lane; i < DD; i += 32) {
            float x = src[i] * inv;
            __half h = __float2half(x);
            float hf = __half2float(h);
            g_pnh[(size_t)j*DD + i] = h;
            g_pn2[(size_t)j*DD + i] = __float2half(fmaf(64.0f, x - hf, hf));
        }
    }
}

// ---------------------------------------------------------------------------
// sw = softmax(sa_weights, axis=-1) * K
// ---------------------------------------------------------------------------
__global__ void sw_kernel(const float* __restrict__ sa) {
    int c = blockIdx.x * blockDim.x + threadIdx.x;
    if (c >= NCLS) return;
    float w[KP];
    float m = -1e30f;
    for (int k = 0; k < KP; k++) { w[k] = sa[c*KP+k]; m = fmaxf(m, w[k]); }
    float s = 0.0f;
    for (int k = 0; k < KP; k++) { w[k] = expf(w[k]-m); s += w[k]; }
    for (int k = 0; k < KP; k++) g_sw[c*KP+k] = w[k] / s * 5.0f;
}

// ---------------------------------------------------------------------------
// 2-product fp16 GEMM (Ootomo, product-split warps):  out = P0 + (P1-P0)/64
// CTA 128x128, 512 thr = 16 warps; BK=64, 2-stage cp.async.  (R12 config)
// ---------------------------------------------------------------------------
#define SAS2 72
#define ROW_B 144
#define ARR_B (128*ROW_B)                    // 18432 per array
#define STAGE_B (4*ARR_B)                    // 73728 per stage
#define SMEM_GEMM (2*STAGE_B)                // 147456
#define NCHUNK (DD/64)                       // 12

__global__ __launch_bounds__(512, 1) void gemm_mma_kernel(float* __restrict__ out) {
    extern __shared__ __align__(16) char smem[];
    const uint32_t sb = (uint32_t)__cvta_generic_to_shared(smem);

    const int tid  = threadIdx.x;
    const int lane = tid & 31;
    const int wid  = tid >> 5;
    const int p    = wid >> 3;
    const int t    = wid & 7;
    const int wm   = t & 3;
    const int wn   = t >> 2;
    const int bm   = blockIdx.x * 128;
    const int bn   = blockIdx.y * 128;

    const int arow = (lane & 7) + ((lane >> 3) & 1) * 8;
    const int acol = (lane >> 4) * 8;
    const int brow = (lane & 7) + ((lane >> 4) & 1) * 8;
    const int bcol = ((lane >> 3) & 1) * 8;

    const uint32_t offA = (uint32_t)p * ARR_B;
    const uint32_t offB = (uint32_t)(2 + p) * ARR_B;

    float acc[2][8][4];
    #pragma unroll
    for (int i = 0; i < 2; i++)
        #pragma unroll
        for (int j = 0; j < 8; j++)
            #pragma unroll
            for (int q = 0; q < 4; q++) acc[i][j][q] = 0.0f;

    auto load_chunk = [&](int kt, int s) {
        uint32_t st = sb + s*STAGE_B;
        #pragma unroll
        for (int i = 0; i < 8; i++) {
            int x = i*512 + tid;
            int arr = x >> 10;
            int rem = x & 1023;
            int row = rem >> 3, q = rem & 7;
            uint32_t dst = st + arr*ARR_B + (uint32_t)(row*ROW_B + q*16);
            const __half* src;
            if (arr == 0)      src = g_pth + (size_t)(bm + row)*DD;
            else if (arr == 1) src = g_pt2 + (size_t)(bm + row)*DD;
            else if (arr == 2) src = g_pnh + (size_t)(bn + row)*DD;
            else               src = g_pn2 + (size_t)(bn + row)*DD;
            cpa16(dst, src + kt + q*8);
        }
        cpa_commit();
    };

    load_chunk(0, 0);

    for (int i = 0; i < NCHUNK; i++) {
        const int s = i & 1;
        if (i + 1 < NCHUNK) {
            load_chunk((i+1)*64, (i+1) & 1);
            cpa_wait<1>();
        } else {
            cpa_wait<0>();
        }
        __syncthreads();

        const uint32_t aA = sb + s*STAGE_B + offA;
        const uint32_t aB = sb + s*STAGE_B + offB;

        #pragma unroll
        for (int ks = 0; ks < 64; ks += 16) {
            uint32_t af[2][4];
            #pragma unroll
            for (int mi = 0; mi < 2; mi++) {
                uint32_t off = (uint32_t)((wm*32 + mi*16 + arow)*SAS2 + ks + acol) * 2;
                ldsm_x4(af[mi], aA + off);
            }
            #pragma unroll
            for (int nb = 0; nb < 4; nb++) {
                uint32_t bf[4];
                uint32_t off = (uint32_t)((wn*64 + nb*16 + brow)*SAS2 + ks + bcol) * 2;
                ldsm_x4(bf, aB + off);
                #pragma unroll
                for (int mi = 0; mi < 2; mi++) {
                    mma_fp16(acc[mi][nb*2+0], af[mi], bf+0);
                    mma_fp16(acc[mi][nb*2+1], af[mi], bf+2);
                }
            }
        }
        __syncthreads();
    }

    float* xbuf = (float*)smem;
    if (p == 1) {
        float* tb = xbuf + t*2048;
        #pragma unroll
        for (int mi = 0; mi < 2; mi++)
            #pragma unroll
            for (int nf = 0; nf < 8; nf++)
                #pragma unroll
                for (int q = 0; q < 4; q++) {
                    int row = mi*16 + (lane >> 2) + (q >> 1)*8;
                    int col = nf*8 + (lane & 3)*2 + (q & 1);
                    tb[row*64 + col] = acc[mi][nf][q];
                }
    }
    __syncthreads();
    if (p == 0) {
        const float* tb = xbuf + t*2048;
        #pragma unroll
        for (int mi = 0; mi < 2; mi++)
            #pragma unroll
            for (int nf = 0; nf < 8; nf++)
                #pragma unroll
                for (int q = 0; q < 4; q++) {
                    int rloc = mi*16 + (lane >> 2) + (q >> 1)*8;
                    int cloc = nf*8 + (lane & 3)*2 + (q & 1);
                    int col = bn + wn*64 + cloc;
                    if (col < JJ) {
                        float p0 = acc[mi][nf][q];
                        float p1 = tb[rloc*64 + cloc];
                        out[(size_t)(bm + wm*32 + rloc)*JJ + col] =
                            p0 + (p1 - p0) * 0.015625f;
                    }
                }
    }
}

// ---------------------------------------------------------------------------
// image_logits[b, j] = max_p logits[b, p, j]  (4 independent max chains)
// ---------------------------------------------------------------------------
__global__ void imgmax_kernel(const float* __restrict__ logits, float* __restrict__ img) {
    int t = blockIdx.x * blockDim.x + threadIdx.x;
    if (t >= BB*JJ) return;
    int b = t / JJ, j = t % JJ;
    const float* p = logits + (size_t)b*PP*JJ + j;
    float m0 = -1e30f, m1 = -1e30f, m2 = -1e30f, m3 = -1e30f;
    for (int i = 0; i < PP; i += 4) {         // 196 = 4*49
        m0 = fmaxf(m0, p[(size_t)(i+0)*JJ]);
        m1 = fmaxf(m1, p[(size_t)(i+1)*JJ]);
        m2 = fmaxf(m2, p[(size_t)(i+2)*JJ]);
        m3 = fmaxf(m3, p[(size_t)(i+3)*JJ]);
    }
    img[(size_t)b*JJ + j] = fmaxf(fmaxf(m0, m1), fmaxf(m2, m3));
}

// ---------------------------------------------------------------------------
// class_logits[b, c] = sum_k img[b, c, k]*sw[c, k] / TEMP
// ---------------------------------------------------------------------------
__global__ void cls_kernel(const float* __restrict__ img, float* __restrict__ cls) {
    int t = blockIdx.x * blockDim.x + threadIdx.x;
    if (t >= BB*NCLS) return;
    int b = t / NCLS, c = t % NCLS;
    float s = 0.0f;
    #pragma unroll
    for (int k = 0; k < KP; k++) s += img[(size_t)b*JJ + c*KP + k] * g_sw[c*KP+k];
    cls[t] = s / 0.2f;
}

// ---------------------------------------------------------------------------
// Per-class Sinkhorn: 2-phase ballot compaction; fused row+col normalization
// (2 syncs/iter); argmax fold; ILP-4 P_new.
// ---------------------------------------------------------------------------
#define MAXN 1024
__global__ __launch_bounds__(256) void sinkhorn_kernel(
        const float* __restrict__ logits, const int* __restrict__ labels,
        const float* __restrict__ proto, const float* __restrict__ rpt,
        float* __restrict__ assign, float* __restrict__ pnew) {
    const int c = blockIdx.x;
    const int tid = threadIdx.x;
    const int lane = tid & 31, w = tid >> 5;

    __shared__ int      s_idx[MAXN];
    __shared__ float    Q[KP][MAXN];
    __shared__ unsigned s_ball[NBATCH*8];
    __shared__ int      s_boff[NBATCH*8];
    __shared__ float    s_red[8*KP];
    __shared__ float    s_tot[8];
    __shared__ int      s_n;

    // phase A: ballots (no intermediate syncs)
    unsigned myball[NBATCH];
    #pragma unroll 7
    for (int b = 0; b < NBATCH; b++) {
        int n = b*256 + tid;
        bool p = (labels[n] == c);
        myball[b] = __ballot_sync(0xffffffffu, p);
        if (lane == 0) s_ball[b*8 + w] = myball[b];
    }
    __syncthreads();
    if (tid == 0) {
        int s = 0;
        for (int i = 0; i < NBATCH*8; i++) { s_boff[i] = s; s += __popc(s_ball[i]); }
        s_n = s;
    }
    __syncthreads();
    const int Nc = min(s_n, MAXN);

    if (Nc == 0) {
        for (int x = tid; x < KP*DD; x += 256)
            pnew[(size_t)c*KP*DD + x] = proto[(size_t)c*KP*DD + x];
        return;
    }

    // phase B: positions from registers (no reloads)
    #pragma unroll 7
    for (int b = 0; b < NBATCH; b++) {
        unsigned bal = myball[b];
        if ((bal >> lane) & 1u) {
            int pos = s_boff[b*8 + w] + __popc(bal & ((1u << lane) - 1u));
            if (pos < MAXN) s_idx[pos] = b*256 + tid;
        }
    }
    __syncthreads();

    // exp + global sum (fused)
    float part = 0.0f;
    for (int i = tid; i < Nc; i += 256) {
        const float* lp = logits + (size_t)s_idx[i]*JJ + c*KP;
        #pragma unroll
        for (int k = 0; k < KP; k++) {
            float e = expf(lp[k] * 20.0f);
            Q[k][i] = e;
            part += e;
        }
    }
    #pragma unroll
    for (int o = 16; o > 0; o >>= 1) part += __shfl_xor_sync(0xffffffffu, part, o);
    if (lane == 0) s_tot[w] = part;
    __syncthreads();
    float tot = 0.0f;
    #pragma unroll
    for (int q = 0; q < 8; q++) tot += s_tot[q];
    float dTot = (tot > 0.0f) ? tot : 1.0f;
    for (int i = tid; i < Nc; i += 256)
        #pragma unroll
        for (int k = 0; k < KP; k++) Q[k][i] /= dTot;
    __syncthreads();

    const float fNc = (float)Nc;
    for (int it = 0; it < 3; it++) {
        // one pass: all 5 row sums
        float rs[KP] = {0.f, 0.f, 0.f, 0.f, 0.f};
        for (int i = tid; i < Nc; i += 256)
            #pragma unroll
            for (int k = 0; k < KP; k++) rs[k] += Q[k][i];
        #pragma unroll
        for (int k = 0; k < KP; k++)
            #pragma unroll
            for (int o = 16; o > 0; o >>= 1)
                rs[k] += __shfl_xor_sync(0xffffffffu, rs[k], o);
        if (lane == 0)
            #pragma unroll
            for (int k = 0; k < KP; k++) s_red[w*KP + k] = rs[k];
        __syncthreads();
        float dr[KP];
        #pragma unroll
        for (int k = 0; k < KP; k++) {
            float r = 0.0f;
            #pragma unroll
            for (int q = 0; q < 8; q++) r += s_red[q*KP + k];
            dr[k] = ((r > 0.0f) ? r : 1.0f) * 5.0f;
        }
        // fused row update + column normalization
        for (int i = tid; i < Nc; i += 256) {
            float q[KP], cs = 0.0f;
            #pragma unroll
            for (int k = 0; k < KP; k++) { q[k] = Q[k][i] / dr[k]; cs += q[k]; }
            float dc = ((cs > 0.0f) ? cs : 1.0f) * fNc;
            #pragma unroll
            for (int k = 0; k < KP; k++) Q[k][i] = q[k] / dc;
        }
        __syncthreads();
    }

    // argmax (invariant to the uniform *Nc undo) + fold fNc*inv into Q
    for (int i = tid; i < Nc; i += 256) {
        float best = Q[0][i]; int ba = 0;
        #pragma unroll
        for (int k = 1; k < KP; k++) if (Q[k][i] > best) { best = Q[k][i]; ba = k; }
        assign[s_idx[i]] = (float)(c*KP + ba);
        float f = fNc * g_inv[s_idx[i]];
        #pragma unroll
        for (int k = 0; k < KP; k++) Q[k][i] *= f;
    }
    __syncthreads();

    // P_new with ILP-4 over i
    const int d0 = tid * 3;
    float acc[KP][3];
    #pragma unroll
    for (int k = 0; k < KP; k++) { acc[k][0]=0.f; acc[k][1]=0.f; acc[k][2]=0.f; }
    int i = 0;
    for (; i + 4 <= Nc; i += 4) {
        const float* xp0 = rpt + (size_t)s_idx[i+0]*DD + d0;
        const float* xp1 = rpt + (size_t)s_idx[i+1]*DD + d0;
        const float* xp2 = rpt + (size_t)s_idx[i+2]*DD + d0;
        const float* xp3 = rpt + (size_t)s_idx[i+3]*DD + d0;
        float a0 = xp0[0], a1 = xp0[1], a2 = xp0[2];
        float b0 = xp1[0], b1 = xp1[1], b2 = xp1[2];
        float c0 = xp2[0], c1 = xp2[1], c2 = xp2[2];
        float e0 = xp3[0], e1 = xp3[1], e2 = xp3[2];
        #pragma unroll
        for (int k = 0; k < KP; k++) {
            float q0 = Q[k][i+0], q1 = Q[k][i+1], q2 = Q[k][i+2], q3 = Q[k][i+3];
            acc[k][0] = fmaf(q0, a0, acc[k][0]);
            acc[k][1] = fmaf(q0, a1, acc[k][1]);
            acc[k][2] = fmaf(q0, a2, acc[k][2]);
            acc[k][0] = fmaf(q1, b0, acc[k][0]);
            acc[k][1] = fmaf(q1, b1, acc[k][1]);
            acc[k][2] = fmaf(q1, b2, acc[k][2]);
            acc[k][0] = fmaf(q2, c0, acc[k][0]);
            acc[k][1] = fmaf(q2, c1, acc[k][1]);
            acc[k][2] = fmaf(q2, c2, acc[k][2]);
            acc[k][0] = fmaf(q3, e0, acc[k][0]);
            acc[k][1] = fmaf(q3, e1, acc[k][1]);
            acc[k][2] = fmaf(q3, e2, acc[k][2]);
        }
    }
    for (; i < Nc; i++) {
        const float* xp = rpt + (size_t)s_idx[i]*DD + d0;
        float x0 = xp[0], x1 = xp[1], x2 = xp[2];
        #pragma unroll
        for (int k = 0; k < KP; k++) {
            float q = Q[k][i];
            acc[k][0] = fmaf(q, x0, acc[k][0]);
            acc[k][1] = fmaf(q, x1, acc[k][1]);
            acc[k][2] = fmaf(q, x2, acc[k][2]);
        }
    }
    const float g = 0.999f, og = 1.0f - 0.999f;
    #pragma unroll
    for (int k = 0; k < KP; k++) {
        size_t basep = ((size_t)c*KP + k)*DD + d0;
        #pragma unroll
        for (int j = 0; j < 3; j++)
            pnew[basep + j] = g * proto[basep + j] + og * acc[k][j];
    }
}

// ---------------------------------------------------------------------------
extern "C" void kernel_launch(void* const* d_in, const int* in_sizes, int n_in,
                              void* d_out, int out_size) {
    const float* pt    = (const float*)d_in[0];
    const float* rpt   = (const float*)d_in[1];
    const float* proto = (const float*)d_in[2];
    const float* sa    = (const float*)d_in[3];
    const int*   lbl   = (const int*)  d_in[4];
    float* out = (float*)d_out;

    cudaFuncSetAttribute(gemm_mma_kernel,
                         cudaFuncAttributeMaxDynamicSharedMemorySize, SMEM_GEMM);

    pad_kernel<<<1, 32>>>();                              // keeps ncu window on GEMM
    norm_kernel<<<(2*NN + JPAD + 7)/8, 256>>>(pt, rpt, proto);
    sw_kernel<<<1, 256>>>(sa);
    {
        dim3 grid(NN/128, JPAD/128);   // 98 x 8
        gemm_mma_kernel<<<grid, 512, SMEM_GEMM>>>(out + OFF_LOGITS);
    }
    imgmax_kernel<<<(BB*JJ + 255)/256, 256>>>(out + OFF_LOGITS, out + OFF_IMG);
    cls_kernel<<<(BB*NCLS + 255)/256, 256>>>(out + OFF_IMG, out + OFF_CLS);
    sinkhorn_kernel<<<CC, 256>>>(out + OFF_LOGITS, lbl, proto, rpt,
                                 out + OFF_ASGN, out + OFF_PNEW);
}

// round 16
// speedup vs baseline: 2.5379x; 1.0525x over previous
#include <cuda_runtime.h>
#include <cuda_fp16.h>
#include <cstdint>
#include <math.h>

// Problem constants
#define BB 64
#define PP 196
#define DD 768
#define CC 201
#define KP 5
#define NCLS 200
#define NN (BB*PP)        // 12544
#define JJ (CC*KP)        // 1005
#define JPAD 1024
#define NBATCH (NN/256)   // 49

// Output layout
#define OFF_LOGITS 0
#define SZ_LOGITS  (NN*JJ)
#define OFF_IMG    (OFF_LOGITS + SZ_LOGITS)
#define SZ_IMG     (BB*JJ)
#define OFF_CLS    (OFF_IMG + SZ_IMG)
#define SZ_CLS     (BB*NCLS)
#define OFF_ASGN   (OFF_CLS + SZ_CLS)
#define SZ_ASGN    (NN)
#define OFF_PNEW   (OFF_ASGN + SZ_ASGN)
#define SZ_PNEW    (CC*KP*DD)

// Device scratch
__device__ __align__(16) __half g_pth[NN*DD];     // fp16(A)
__device__ __align__(16) __half g_pt2[NN*DD];     // fp16(Ah + 64*(A-Ah))
__device__ __align__(16) __half g_pnh[JPAD*DD];   // fp16(B)
__device__ __align__(16) __half g_pn2[JPAD*DD];   // fp16(Bh + 64*(B-Bh))
__device__ float g_inv[NN];                       // 1/||rpt_row||
__device__ float g_sw[NCLS*KP];

// ---------------------------------------------------------------------------
// PTX helpers
// ---------------------------------------------------------------------------
__device__ __forceinline__ void ldsm_x4(uint32_t* r, uint32_t addr) {
    asm volatile("ldmatrix.sync.aligned.m8n8.x4.shared.b16 {%0,%1,%2,%3}, [%4];"
                 : "=r"(r[0]), "=r"(r[1]), "=r"(r[2]), "=r"(r[3]) : "r"(addr));
}
__device__ __forceinline__ void mma_fp16(float* d, const uint32_t* a, const uint32_t* b) {
    asm volatile(
        "mma.sync.aligned.m16n8k16.row.col.f32.f16.f16.f32 "
        "{%0,%1,%2,%3}, {%4,%5,%6,%7}, {%8,%9}, {%0,%1,%2,%3};"
        : "+f"(d[0]), "+f"(d[1]), "+f"(d[2]), "+f"(d[3])
        : "r"(a[0]), "r"(a[1]), "r"(a[2]), "r"(a[3]), "r"(b[0]), "r"(b[1]));
}
__device__ __forceinline__ void cpa16(uint32_t smem, const void* g) {
    asm volatile("cp.async.ca.shared.global [%0], [%1], 16;" :: "r"(smem), "l"(g));
}
__device__ __forceinline__ void cpa_commit() {
    asm volatile("cp.async.commit_group;" ::: "memory");
}
template <int N>
__device__ __forceinline__ void cpa_wait() {
    asm volatile("cp.async.wait_group %0;" :: "n"(N) : "memory");
}
// exact float atomic max (mixed signed-int max / unsigned-int min trick)
__device__ __forceinline__ void atomicMaxF(float* addr, float v) {
    if (v >= 0.0f) atomicMax((int*)addr, __float_as_int(v));
    else           atomicMin((unsigned int*)addr, __float_as_uint(v));
}

// ---------------------------------------------------------------------------
// Row L2 normalization + fp16 Ootomo split (warp per row, float4 loads)
// ---------------------------------------------------------------------------
__global__ __launch_bounds__(256) void norm_kernel(const float* __restrict__ pt,
                            const float* __restrict__ rpt,
                            const float* __restrict__ proto) {
    const int r = blockIdx.x * 8 + (threadIdx.x >> 5);
    const int lane = threadIdx.x & 31;
    if (r >= 2*NN + JPAD) return;

    if (r < NN) {
        const float4* src = (const float4*)(pt + (size_t)r*DD);
        float s = 0.0f;
        float4 v[6];
        #pragma unroll
        for (int i = 0; i < 6; i++) {
            v[i] = src[lane + i*32];
            s += v[i].x*v[i].x + v[i].y*v[i].y + v[i].z*v[i].z + v[i].w*v[i].w;
        }
        #pragma unroll
        for (int o = 16; o > 0; o >>= 1) s += __shfl_xor_sync(0xffffffffu, s, o);
        float inv = 1.0f / fmaxf(sqrtf(s), 1e-12f);
        #pragma unroll
        for (int i = 0; i < 6; i++) {
            float x[4] = {v[i].x*inv, v[i].y*inv, v[i].z*inv, v[i].w*inv};
            __half2 h2[2], l2[2];
            #pragma unroll
            for (int j = 0; j < 2; j++) {
                __half h0 = __float2half(x[j*2]),  h1 = __float2half(x[j*2+1]);
                float f0 = __half2float(h0),        f1 = __half2float(h1);
                h2[j] = __halves2half2(h0, h1);
                l2[j] = __halves2half2(__float2half(fmaf(64.0f, x[j*2]-f0, f0)),
                                       __float2half(fmaf(64.0f, x[j*2+1]-f1, f1)));
            }
            size_t o4 = (size_t)r*DD + (lane + i*32)*4;
            *(__half2*)(g_pth + o4)     = h2[0];
            *(__half2*)(g_pth + o4 + 2) = h2[1];
            *(__half2*)(g_pt2 + o4)     = l2[0];
            *(__half2*)(g_pt2 + o4 + 2) = l2[1];
        }
    } else if (r < 2*NN) {
        int rr = r - NN;
        const float4* src = (const float4*)(rpt + (size_t)rr*DD);
        float s = 0.0f;
        #pragma unroll
        for (int i = 0; i < 6; i++) {
            float4 v = src[lane + i*32];
            s += v.x*v.x + v.y*v.y + v.z*v.z + v.w*v.w;
        }
        #pragma unroll
        for (int o = 16; o > 0; o >>= 1) s += __shfl_xor_sync(0xffffffffu, s, o);
        if (lane == 0) g_inv[rr] = 1.0f / fmaxf(sqrtf(s), 1e-12f);
    } else {
        int j = r - 2*NN;
        if (j >= JJ) {
            __half z = __float2half(0.0f);
            for (int i = lane; i < DD; i += 32) {
                g_pnh[(size_t)j*DD + i] = z;
                g_pn2[(size_t)j*DD + i] = z;
            }
            return;
        }
        const float* src = proto + (size_t)j*DD;
        float s = 0.0f;
        for (int i = lane; i < DD; i += 32) { float v = src[i]; s += v*v; }
        #pragma unroll
        for (int o = 16; o > 0; o >>= 1) s += __shfl_xor_sync(0xffffffffu, s, o);
        float inv = 1.0f / fmaxf(sqrtf(s), 1e-12f);
        for (int i = lane; i < DD; i += 32) {
            float x = src[i] * inv;
            __half h = __float2half(x);
            float hf = __half2float(h);
            g_pnh[(size_t)j*DD + i] = h;
            g_pn2[(size_t)j*DD + i] = __float2half(fmaf(64.0f, x - hf, hf));
        }
    }
}

// ---------------------------------------------------------------------------
// sw = softmax(sa_weights)*K  +  init img buffer to -inf (for atomic max)
// ---------------------------------------------------------------------------
__global__ void sw_kernel(const float* __restrict__ sa, float* __restrict__ img) {
    int t = blockIdx.x * blockDim.x + threadIdx.x;
    if (t < SZ_IMG) img[t] = -INFINITY;
    if (t >= NCLS) return;
    int c = t;
    float w[KP];
    float m = -1e30f;
    for (int k = 0; k < KP; k++) { w[k] = sa[c*KP+k]; m = fmaxf(m, w[k]); }
    float s = 0.0f;
    for (int k = 0; k < KP; k++) { w[k] = expf(w[k]-m); s += w[k]; }
    for (int k = 0; k < KP; k++) g_sw[c*KP+k] = w[k] / s * 5.0f;
}

// ---------------------------------------------------------------------------
// 2-product fp16 GEMM (Ootomo, product-split warps):  out = P0 + (P1-P0)/64
// CTA 128x128, 512 thr = 16 warps; BK=64, 2-stage cp.async.  (R12 config)
// ---------------------------------------------------------------------------
#define SAS2 72
#define ROW_B 144
#define ARR_B (128*ROW_B)                    // 18432 per array
#define STAGE_B (4*ARR_B)                    // 73728 per stage
#define SMEM_GEMM (2*STAGE_B)                // 147456
#define NCHUNK (DD/64)                       // 12

__global__ __launch_bounds__(512, 1) void gemm_mma_kernel(float* __restrict__ out) {
    extern __shared__ __align__(16) char smem[];
    const uint32_t sb = (uint32_t)__cvta_generic_to_shared(smem);

    const int tid  = threadIdx.x;
    const int lane = tid & 31;
    const int wid  = tid >> 5;
    const int p    = wid >> 3;
    const int t    = wid & 7;
    const int wm   = t & 3;
    const int wn   = t >> 2;
    const int bm   = blockIdx.x * 128;
    const int bn   = blockIdx.y * 128;

    const int arow = (lane & 7) + ((lane >> 3) & 1) * 8;
    const int acol = (lane >> 4) * 8;
    const int brow = (lane & 7) + ((lane >> 4) & 1) * 8;
    const int bcol = ((lane >> 3) & 1) * 8;

    const uint32_t offA = (uint32_t)p * ARR_B;
    const uint32_t offB = (uint32_t)(2 + p) * ARR_B;

    float acc[2][8][4];
    #pragma unroll
    for (int i = 0; i < 2; i++)
        #pragma unroll
        for (int j = 0; j < 8; j++)
            #pragma unroll
            for (int q = 0; q < 4; q++) acc[i][j][q] = 0.0f;

    auto load_chunk = [&](int kt, int s) {
        uint32_t st = sb + s*STAGE_B;
        #pragma unroll
        for (int i = 0; i < 8; i++) {
            int x = i*512 + tid;
            int arr = x >> 10;
            int rem = x & 1023;
            int row = rem >> 3, q = rem & 7;
            uint32_t dst = st + arr*ARR_B + (uint32_t)(row*ROW_B + q*16);
            const __half* src;
            if (arr == 0)      src = g_pth + (size_t)(bm + row)*DD;
            else if (arr == 1) src = g_pt2 + (size_t)(bm + row)*DD;
            else if (arr == 2) src = g_pnh + (size_t)(bn + row)*DD;
            else               src = g_pn2 + (size_t)(bn + row)*DD;
            cpa16(dst, src + kt + q*8);
        }
        cpa_commit();
    };

    load_chunk(0, 0);

    for (int i = 0; i < NCHUNK; i++) {
        const int s = i & 1;
        if (i + 1 < NCHUNK) {
            load_chunk((i+1)*64, (i+1) & 1);
            cpa_wait<1>();
        } else {
            cpa_wait<0>();
        }
        __syncthreads();

        const uint32_t aA = sb + s*STAGE_B + offA;
        const uint32_t aB = sb + s*STAGE_B + offB;

        #pragma unroll
        for (int ks = 0; ks < 64; ks += 16) {
            uint32_t af[2][4];
            #pragma unroll
            for (int mi = 0; mi < 2; mi++) {
                uint32_t off = (uint32_t)((wm*32 + mi*16 + arow)*SAS2 + ks + acol) * 2;
                ldsm_x4(af[mi], aA + off);
            }
            #pragma unroll
            for (int nb = 0; nb < 4; nb++) {
                uint32_t bf[4];
                uint32_t off = (uint32_t)((wn*64 + nb*16 + brow)*SAS2 + ks + bcol) * 2;
                ldsm_x4(bf, aB + off);
                #pragma unroll
                for (int mi = 0; mi < 2; mi++) {
                    mma_fp16(acc[mi][nb*2+0], af[mi], bf+0);
                    mma_fp16(acc[mi][nb*2+1], af[mi], bf+2);
                }
            }
        }
        __syncthreads();
    }

    float* xbuf = (float*)smem;
    if (p == 1) {
        float* tb = xbuf + t*2048;
        #pragma unroll
        for (int mi = 0; mi < 2; mi++)
            #pragma unroll
            for (int nf = 0; nf < 8; nf++)
                #pragma unroll
                for (int q = 0; q < 4; q++) {
                    int row = mi*16 + (lane >> 2) + (q >> 1)*8;
                    int col = nf*8 + (lane & 3)*2 + (q & 1);
                    tb[row*64 + col] = acc[mi][nf][q];
                }
    }
    __syncthreads();
    if (p == 0) {
        const float* tb = xbuf + t*2048;
        #pragma unroll
        for (int mi = 0; mi < 2; mi++)
            #pragma unroll
            for (int nf = 0; nf < 8; nf++)
                #pragma unroll
                for (int q = 0; q < 4; q++) {
                    int rloc = mi*16 + (lane >> 2) + (q >> 1)*8;
                    int cloc = nf*8 + (lane & 3)*2 + (q & 1);
                    int col = bn + wn*64 + cloc;
                    if (col < JJ) {
                        float p0 = acc[mi][nf][q];
                        float p1 = tb[rloc*64 + cloc];
                        out[(size_t)(bm + wm*32 + rloc)*JJ + col] =
                            p0 + (p1 - p0) * 0.015625f;
                    }
                }
    }
}

// ---------------------------------------------------------------------------
// image_logits[b, j] = max_p logits[b, p, j]
// 4-way P split + atomic float max (img pre-initialized to -inf)
// ---------------------------------------------------------------------------
__global__ void imgmax_kernel(const float* __restrict__ logits, float* __restrict__ img) {
    int t = blockIdx.x * blockDim.x + threadIdx.x;
    if (t >= BB*JJ*4) return;
    int seg = t / (BB*JJ);
    int r   = t % (BB*JJ);
    int b = r / JJ, j = r % JJ;
    const float* p = logits + (size_t)b*PP*JJ + (size_t)seg*49*JJ + j;
    float m = -1e30f;
    for (int i = 0; i < 49; i++) m = fmaxf(m, p[(size_t)i*JJ]);
    atomicMaxF(&img[(size_t)b*JJ + j], m);
}

// ---------------------------------------------------------------------------
// class_logits[b, c] = sum_k img[b, c, k]*sw[c, k] / TEMP
// ---------------------------------------------------------------------------
__global__ void cls_kernel(const float* __restrict__ img, float* __restrict__ cls) {
    int t = blockIdx.x * blockDim.x + threadIdx.x;
    if (t >= BB*NCLS) return;
    int b = t / NCLS, c = t % NCLS;
    float s = 0.0f;
    #pragma unroll
    for (int k = 0; k < KP; k++) s += img[(size_t)b*JJ + c*KP + k] * g_sw[c*KP+k];
    cls[t] = s / 0.2f;
}

// ---------------------------------------------------------------------------
// Per-class Sinkhorn: 2-phase ballot compaction; fused row+col normalization;
// argmax fold; ILP-4 P_new.   (R15 version)
// ---------------------------------------------------------------------------
#define MAXN 1024
__global__ __launch_bounds__(256) void sinkhorn_kernel(
        const float* __restrict__ logits, const int* __restrict__ labels,
        const float* __restrict__ proto, const float* __restrict__ rpt,
        float* __restrict__ assign, float* __restrict__ pnew) {
    const int c = blockIdx.x;
    const int tid = threadIdx.x;
    const int lane = tid & 31, w = tid >> 5;

    __shared__ int      s_idx[MAXN];
    __shared__ float    Q[KP][MAXN];
    __shared__ unsigned s_ball[NBATCH*8];
    __shared__ int      s_boff[NBATCH*8];
    __shared__ float    s_red[8*KP];
    __shared__ float    s_tot[8];
    __shared__ int      s_n;

    unsigned myball[NBATCH];
    #pragma unroll 7
    for (int b = 0; b < NBATCH; b++) {
        int n = b*256 + tid;
        bool p = (labels[n] == c);
        myball[b] = __ballot_sync(0xffffffffu, p);
        if (lane == 0) s_ball[b*8 + w] = myball[b];
    }
    __syncthreads();
    if (tid == 0) {
        int s = 0;
        for (int i = 0; i < NBATCH*8; i++) { s_boff[i] = s; s += __popc(s_ball[i]); }
        s_n = s;
    }
    __syncthreads();
    const int Nc = min(s_n, MAXN);

    if (Nc == 0) {
        for (int x = tid; x < KP*DD; x += 256)
            pnew[(size_t)c*KP*DD + x] = proto[(size_t)c*KP*DD + x];
        return;
    }

    #pragma unroll 7
    for (int b = 0; b < NBATCH; b++) {
        unsigned bal = myball[b];
        if ((bal >> lane) & 1u) {
            int pos = s_boff[b*8 + w] + __popc(bal & ((1u << lane) - 1u));
            if (pos < MAXN) s_idx[pos] = b*256 + tid;
        }
    }
    __syncthreads();

    float part = 0.0f;
    for (int i = tid; i < Nc; i += 256) {
        const float* lp = logits + (size_t)s_idx[i]*JJ + c*KP;
        #pragma unroll
        for (int k = 0; k < KP; k++) {
            float e = expf(lp[k] * 20.0f);
            Q[k][i] = e;
            part += e;
        }
    }
    #pragma unroll
    for (int o = 16; o > 0; o >>= 1) part += __shfl_xor_sync(0xffffffffu, part, o);
    if (lane == 0) s_tot[w] = part;
    __syncthreads();
    float tot = 0.0f;
    #pragma unroll
    for (int q = 0; q < 8; q++) tot += s_tot[q];
    float dTot = (tot > 0.0f) ? tot : 1.0f;
    for (int i = tid; i < Nc; i += 256)
        #pragma unroll
        for (int k = 0; k < KP; k++) Q[k][i] /= dTot;
    __syncthreads();

    const float fNc = (float)Nc;
    for (int it = 0; it < 3; it++) {
        float rs[KP] = {0.f, 0.f, 0.f, 0.f, 0.f};
        for (int i = tid; i < Nc; i += 256)
            #pragma unroll
            for (int k = 0; k < KP; k++) rs[k] += Q[k][i];
        #pragma unroll
        for (int k = 0; k < KP; k++)
            #pragma unroll
            for (int o = 16; o > 0; o >>= 1)
                rs[k] += __shfl_xor_sync(0xffffffffu, rs[k], o);
        if (lane == 0)
            #pragma unroll
            for (int k = 0; k < KP; k++) s_red[w*KP + k] = rs[k];
        __syncthreads();
        float dr[KP];
        #pragma unroll
        for (int k = 0; k < KP; k++) {
            float r = 0.0f;
            #pragma unroll
            for (int q = 0; q < 8; q++) r += s_red[q*KP + k];
            dr[k] = ((r > 0.0f) ? r : 1.0f) * 5.0f;
        }
        for (int i = tid; i < Nc; i += 256) {
            float q[KP], cs = 0.0f;
            #pragma unroll
            for (int k = 0; k < KP; k++) { q[k] = Q[k][i] / dr[k]; cs += q[k]; }
            float dc = ((cs > 0.0f) ? cs : 1.0f) * fNc;
            #pragma unroll
            for (int k = 0; k < KP; k++) Q[k][i] = q[k] / dc;
        }
        __syncthreads();
    }

    for (int i = tid; i < Nc; i += 256) {
        float best = Q[0][i]; int ba = 0;
        #pragma unroll
        for (int k = 1; k < KP; k++) if (Q[k][i] > best) { best = Q[k][i]; ba = k; }
        assign[s_idx[i]] = (float)(c*KP + ba);
        float f = fNc * g_inv[s_idx[i]];
        #pragma unroll
        for (int k = 0; k < KP; k++) Q[k][i] *= f;
    }
    __syncthreads();

    const int d0 = tid * 3;
    float acc[KP][3];
    #pragma unroll
    for (int k = 0; k < KP; k++) { acc[k][0]=0.f; acc[k][1]=0.f; acc[k][2]=0.f; }
    int i = 0;
    for (; i + 4 <= Nc; i += 4) {
        const float* xp0 = rpt + (size_t)s_idx[i+0]*DD + d0;
        const float* xp1 = rpt + (size_t)s_idx[i+1]*DD + d0;
        const float* xp2 = rpt + (size_t)s_idx[i+2]*DD + d0;
        const float* xp3 = rpt + (size_t)s_idx[i+3]*DD + d0;
        float a0 = xp0[0], a1 = xp0[1], a2 = xp0[2];
        float b0 = xp1[0], b1 = xp1[1], b2 = xp1[2];
        float c0 = xp2[0], c1 = xp2[1], c2 = xp2[2];
        float e0 = xp3[0], e1 = xp3[1], e2 = xp3[2];
        #pragma unroll
        for (int k = 0; k < KP; k++) {
            float q0 = Q[k][i+0], q1 = Q[k][i+1], q2 = Q[k][i+2], q3 = Q[k][i+3];
            acc[k][0] = fmaf(q0, a0, acc[k][0]);
            acc[k][1] = fmaf(q0, a1, acc[k][1]);
            acc[k][2] = fmaf(q0, a2, acc[k][2]);
            acc[k][0] = fmaf(q1, b0, acc[k][0]);
            acc[k][1] = fmaf(q1, b1, acc[k][1]);
            acc[k][2] = fmaf(q1, b2, acc[k][2]);
            acc[k][0] = fmaf(q2, c0, acc[k][0]);
            acc[k][1] = fmaf(q2, c1, acc[k][1]);
            acc[k][2] = fmaf(q2, c2, acc[k][2]);
            acc[k][0] = fmaf(q3, e0, acc[k][0]);
            acc[k][1] = fmaf(q3, e1, acc[k][1]);
            acc[k][2] = fmaf(q3, e2, acc[k][2]);
        }
    }
    for (; i < Nc; i++) {
        const float* xp = rpt + (size_t)s_idx[i]*DD + d0;
        float x0 = xp[0], x1 = xp[1], x2 = xp[2];
        #pragma unroll
        for (int k = 0; k < KP; k++) {
            float q = Q[k][i];
            acc[k][0] = fmaf(q, x0, acc[k][0]);
            acc[k][1] = fmaf(q, x1, acc[k][1]);
            acc[k][2] = fmaf(q, x2, acc[k][2]);
        }
    }
    const float g = 0.999f, og = 1.0f - 0.999f;
    #pragma unroll
    for (int k = 0; k < KP; k++) {
        size_t basep = ((size_t)c*KP + k)*DD + d0;
        #pragma unroll
        for (int j = 0; j < 3; j++)
            pnew[basep + j] = g * proto[basep + j] + og * acc[k][j];
    }
}

// ---------------------------------------------------------------------------
extern "C" void kernel_launch(void* const* d_in, const int* in_sizes, int n_in,
                              void* d_out, int out_size) {
    const float* pt    = (const float*)d_in[0];
    const float* rpt   = (const float*)d_in[1];
    const float* proto = (const float*)d_in[2];
    const float* sa    = (const float*)d_in[3];
    const int*   lbl   = (const int*)  d_in[4];
    float* out = (float*)d_out;

    // one-time host-side resources (no device memory; identical work per call)
    static cudaStream_t s2 = nullptr;
    static cudaEvent_t  evFork = nullptr, evJoin = nullptr;
    if (s2 == nullptr) {
        cudaStreamCreateWithFlags(&s2, cudaStreamNonBlocking);
        cudaEventCreateWithFlags(&evFork, cudaEventDisableTiming);
        cudaEventCreateWithFlags(&evJoin, cudaEventDisableTiming);
        cudaFuncSetAttribute(gemm_mma_kernel,
                             cudaFuncAttributeMaxDynamicSharedMemorySize, SMEM_GEMM);
    }

    norm_kernel<<<(2*NN + JPAD + 7)/8, 256>>>(pt, rpt, proto);
    sw_kernel<<<(SZ_IMG + 255)/256, 256>>>(sa, out + OFF_IMG);
    {
        dim3 grid(NN/128, JPAD/128);   // 98 x 8
        gemm_mma_kernel<<<grid, 512, SMEM_GEMM>>>(out + OFF_LOGITS);
    }

    // fork: sinkhorn on s2, imgmax+cls on the main stream
    cudaEventRecord(evFork, 0);
    cudaStreamWaitEvent(s2, evFork, 0);
    sinkhorn_kernel<<<CC, 256, 0, s2>>>(out + OFF_LOGITS, lbl, proto, rpt,
                                        out + OFF_ASGN, out + OFF_PNEW);
    cudaEventRecord(evJoin, s2);

    imgmax_kernel<<<(BB*JJ*4 + 255)/256, 256>>>(out + OFF_LOGITS, out + OFF_IMG);
    cls_kernel<<<(BB*NCLS + 255)/256, 256>>>(out + OFF_IMG, out + OFF_CLS);

    // join
    cudaStreamWaitEvent(0, evJoin, 0);
}